// round 2
// baseline (speedup 1.0000x reference)
#include <cuda_runtime.h>
#include <math.h>

// Problem constants
#define BN_  512      // batch (docs)
#define VV   50000    // vocab
#define KK   200      // topics
#define HH   300      // embed dim
#define HIDD 800      // hidden

#define K1_SPLIT 6
#define K4_SPLIT 24
#define KT_TOTAL (VV/16)          // 3125
#define KT1_PER_Z ((KT_TOTAL + K1_SPLIT - 1)/K1_SPLIT)   // 521
#define KT4_PER_Z ((KT_TOTAL + K4_SPLIT - 1)/K4_SPLIT)   // 131

#define VT ((VV + 63)/64)         // 782 v-tiles
#define NPART (VT*8)              // 6256 partials for fwd/tm

// ---------------- scratch (device globals; no allocation allowed) ----------------
__device__ float g_hid[BN_*HIDD];
__device__ float g_theta[BN_*KK];
__device__ float g_tn[BN_*KK];
__device__ float g_theta2[BN_*KK];
__device__ float g_dis[VV*KK];
__device__ float g_colsum[BN_*KK];
__device__ float g_ntok[BN_];
__device__ float g_invn[BN_];
__device__ float g_S[KK];
__device__ float g_Spart[100*KK];
__device__ float g_part1[K1_SPLIT*BN_*HIDD];
__device__ float g_part4[K4_SPLIT*BN_*KK];
__device__ float g_partF[NPART];
__device__ float g_partT[NPART];
__device__ float g_partB[BN_];

__constant__ float c_lg[5] = {0.0f, 0.0f, 0.69314718055994531f,
                              1.79175946922805500f, 3.17805383034794562f};

// ---------------- n_tok per doc ----------------
__global__ void k_ntok(const float* __restrict__ bows) {
    int b = blockIdx.x, t = threadIdx.x;
    float s = 0.f;
    for (int v = t; v < VV; v += 256) s += bows[(size_t)b*VV + v];
    __shared__ float red[256];
    red[t] = s; __syncthreads();
    for (int st = 128; st > 0; st >>= 1) { if (t < st) red[t] += red[t+st]; __syncthreads(); }
    if (t == 0) { float n = red[0]; g_ntok[b] = n; g_invn[b] = (n > 0.f) ? 1.f/n : 0.f; }
}

// ---------------- GEMM A(M,K) @ B(K,N), split-K partials ----------------
// WHICH=0: hid partials (A=bows, B=W1, N=800), WHICH=1: colsum partials (A=bows, B=g_dis, N=200)
template<int WHICH>
__global__ void gemm_ab(const float* __restrict__ A, const float* __restrict__ Bp) {
    constexpr int M = BN_;
    constexpr int N = (WHICH == 0) ? HIDD : KK;
    constexpr int Kd = VV;
    constexpr int KTPZ = (WHICH == 0) ? KT1_PER_Z : KT4_PER_Z;
    const float* B = (WHICH == 0) ? Bp : (const float*)g_dis;
    float* Cpart = (WHICH == 0) ? g_part1 : g_part4;

    __shared__ __align__(16) float As[16][68];
    __shared__ __align__(16) float Bs[16][68];
    const int tid = threadIdx.x;
    const int tx = tid & 15, ty = tid >> 4;
    const int m0 = blockIdx.y * 64, n0 = blockIdx.x * 64;
    const int z = blockIdx.z;
    const int kt0 = z * KTPZ;
    const int kt1 = min(kt0 + KTPZ, KT_TOTAL);
    const int ar = tid >> 2, ac = (tid & 3) << 2;
    const int br = tid >> 4, bc = (tid & 15) << 2;

    float acc[4][4];
    #pragma unroll
    for (int i = 0; i < 4; i++)
        #pragma unroll
        for (int j = 0; j < 4; j++) acc[i][j] = 0.f;

    for (int kt = kt0; kt < kt1; ++kt) {
        int k0 = kt * 16;
        {   // A tile 64x16 (Kd % 16 == 0, m always < M=512)
            float4 v = *reinterpret_cast<const float4*>(A + (size_t)(m0+ar)*Kd + k0 + ac);
            As[ac+0][ar] = v.x; As[ac+1][ar] = v.y; As[ac+2][ar] = v.z; As[ac+3][ar] = v.w;
        }
        {   // B tile 16x64
            float4 v = make_float4(0.f,0.f,0.f,0.f);
            int gk = k0 + br, gn = n0 + bc;
            const float* bp = B + (size_t)gk*N + gn;
            if (gn + 3 < N) v = *reinterpret_cast<const float4*>(bp);
            else {
                if (gn + 0 < N) v.x = bp[0];
                if (gn + 1 < N) v.y = bp[1];
                if (gn + 2 < N) v.z = bp[2];
            }
            *reinterpret_cast<float4*>(&Bs[br][bc]) = v;
        }
        __syncthreads();
        #pragma unroll
        for (int k = 0; k < 16; k++) {
            float4 a = *reinterpret_cast<const float4*>(&As[k][ty << 2]);
            float4 b = *reinterpret_cast<const float4*>(&Bs[k][tx << 2]);
            float av[4] = {a.x, a.y, a.z, a.w};
            float bv[4] = {b.x, b.y, b.z, b.w};
            #pragma unroll
            for (int i = 0; i < 4; i++)
                #pragma unroll
                for (int j = 0; j < 4; j++)
                    acc[i][j] = fmaf(av[i], bv[j], acc[i][j]);
        }
        __syncthreads();
    }

    float* Cz = Cpart + (size_t)z * M * N;
    #pragma unroll
    for (int i = 0; i < 4; i++) {
        int m = m0 + (ty << 2) + i;          // < 512 always
        int n = n0 + (tx << 2);
        float* row = Cz + (size_t)m*N + n;
        if (n + 3 < N)
            *reinterpret_cast<float4*>(row) = make_float4(acc[i][0], acc[i][1], acc[i][2], acc[i][3]);
        else {
            #pragma unroll
            for (int j = 0; j < 4; j++) if (n + j < N) row[j] = acc[i][j];
        }
    }
}

__global__ void k1_reduce(const float* __restrict__ b1) {
    int idx = blockIdx.x * 256 + threadIdx.x;
    if (idx >= BN_*HIDD) return;
    float s = 0.f;
    #pragma unroll
    for (int z = 0; z < K1_SPLIT; z++) s += g_part1[(size_t)z*BN_*HIDD + idx];
    g_hid[idx] = fmaxf(s + b1[idx % HIDD], 0.f);
}

__global__ void k4_reduce() {
    int idx = blockIdx.x * 256 + threadIdx.x;
    if (idx >= BN_*KK) return;
    float s = 0.f;
    #pragma unroll
    for (int z = 0; z < K4_SPLIT; z++) s += g_part4[(size_t)z*BN_*KK + idx];
    g_colsum[idx] = s;
}

// ---------------- theta = softplus(hid@W2+b2); tn = softmax(theta) ----------------
__global__ void k_theta(const float* __restrict__ W2, const float* __restrict__ b2) {
    int b = blockIdx.x, t = threadIdx.x;
    __shared__ float sh[HIDD];
    __shared__ float red[256];
    for (int h = t; h < HIDD; h += 256) sh[h] = g_hid[(size_t)b*HIDD + h];
    __syncthreads();
    float th = -1e30f;
    if (t < KK) {
        float acc = b2[t];
        #pragma unroll 4
        for (int h = 0; h < HIDD; h++) acc = fmaf(sh[h], W2[(size_t)h*KK + t], acc);
        th = fmaxf(acc, 0.f) + log1pf(expf(-fabsf(acc)));   // softplus = logaddexp(x,0)
        g_theta[(size_t)b*KK + t] = th;
    }
    red[t] = th; __syncthreads();
    for (int s = 128; s > 0; s >>= 1) { if (t < s) red[t] = fmaxf(red[t], red[t+s]); __syncthreads(); }
    float mx = red[0]; __syncthreads();
    float e = (t < KK) ? expf(th - mx) : 0.f;
    red[t] = e; __syncthreads();
    for (int s = 128; s > 0; s >>= 1) { if (t < s) red[t] += red[t+s]; __syncthreads(); }
    float sm = red[0];
    if (t < KK) g_tn[(size_t)b*KK + t] = e / sm;
}

// ---------------- GEMM C = A(M,Kd) @ B(N,Kd)^T with fused epilogues ----------------
// EPI=0: inner=rho@alpha^T -> dis=clip(exp(inner))       (M=VV, N=KK, Kd=HH)
// EPI=1: den^T = tn@dis^T, fused forward reduction       (M=BN_, N=VV, Kd=KK)
// EPI=2: recon = theta2@dis^T, fused Poisson reduction   (M=BN_, N=VV, Kd=KK)
template<int EPI>
__global__ void gemm_abt(const float* __restrict__ Ain, const float* __restrict__ Bin,
                         const float* __restrict__ bows) {
    constexpr int M  = (EPI == 0) ? VV : BN_;
    constexpr int N  = (EPI == 0) ? KK : VV;
    constexpr int Kd = (EPI == 0) ? HH : KK;
    const float* A = (EPI == 0) ? Ain : ((EPI == 1) ? (const float*)g_tn : (const float*)g_theta2);
    const float* B = (EPI == 0) ? Bin : (const float*)g_dis;

    __shared__ __align__(16) float As[16][68];
    __shared__ __align__(16) float Bs[16][68];
    const int tid = threadIdx.x;
    const int tx = tid & 15, ty = tid >> 4;
    const int m0 = blockIdx.y * 64, n0 = blockIdx.x * 64;
    const int ar = tid >> 2, ac = (tid & 3) << 2;
    constexpr int ktTotal = (Kd + 15) / 16;

    float acc[4][4];
    #pragma unroll
    for (int i = 0; i < 4; i++)
        #pragma unroll
        for (int j = 0; j < 4; j++) acc[i][j] = 0.f;

    for (int kt = 0; kt < ktTotal; ++kt) {
        int k0 = kt * 16;
        {   // A tile (rows m, cols k) -> transposed
            float4 v = make_float4(0.f,0.f,0.f,0.f);
            int gm = m0 + ar, gk = k0 + ac;
            if (gm < M) {
                const float* p = A + (size_t)gm*Kd + gk;
                if (gk + 3 < Kd) v = *reinterpret_cast<const float4*>(p);
                else {
                    if (gk + 0 < Kd) v.x = p[0];
                    if (gk + 1 < Kd) v.y = p[1];
                    if (gk + 2 < Kd) v.z = p[2];
                }
            }
            As[ac+0][ar] = v.x; As[ac+1][ar] = v.y; As[ac+2][ar] = v.z; As[ac+3][ar] = v.w;
        }
        {   // B tile (rows n, cols k) -> transposed
            float4 v = make_float4(0.f,0.f,0.f,0.f);
            int gn = n0 + ar, gk = k0 + ac;
            if (gn < N) {
                const float* p = B + (size_t)gn*Kd + gk;
                if (gk + 3 < Kd) v = *reinterpret_cast<const float4*>(p);
                else {
                    if (gk + 0 < Kd) v.x = p[0];
                    if (gk + 1 < Kd) v.y = p[1];
                    if (gk + 2 < Kd) v.z = p[2];
                }
            }
            Bs[ac+0][ar] = v.x; Bs[ac+1][ar] = v.y; Bs[ac+2][ar] = v.z; Bs[ac+3][ar] = v.w;
        }
        __syncthreads();
        #pragma unroll
        for (int k = 0; k < 16; k++) {
            float4 a = *reinterpret_cast<const float4*>(&As[k][ty << 2]);
            float4 b = *reinterpret_cast<const float4*>(&Bs[k][tx << 2]);
            float av[4] = {a.x, a.y, a.z, a.w};
            float bv[4] = {b.x, b.y, b.z, b.w};
            #pragma unroll
            for (int i = 0; i < 4; i++)
                #pragma unroll
                for (int j = 0; j < 4; j++)
                    acc[i][j] = fmaf(av[i], bv[j], acc[i][j]);
        }
        __syncthreads();
    }

    if constexpr (EPI == 0) {
        #pragma unroll
        for (int i = 0; i < 4; i++) {
            int m = m0 + (ty << 2) + i;
            if (m >= M) continue;
            int n = n0 + (tx << 2);
            float o[4];
            #pragma unroll
            for (int j = 0; j < 4; j++)
                o[j] = fminf(fmaxf(expf(acc[i][j]), 1e-30f), 1e10f);
            float* row = g_dis + (size_t)m*N + n;
            if (n + 3 < N) *reinterpret_cast<float4*>(row) = make_float4(o[0], o[1], o[2], o[3]);
            else { 
                #pragma unroll
                for (int j = 0; j < 4; j++) if (n + j < N) row[j] = o[j];
            }
        }
    } else {
        float local = 0.f;
        #pragma unroll
        for (int i = 0; i < 4; i++) {
            int b = m0 + (ty << 2) + i;          // doc index (< 512 always)
            int v0 = n0 + (tx << 2);
            float wv[4] = {0.f, 0.f, 0.f, 0.f};
            if (v0 + 3 < VV) {
                float4 w4 = *reinterpret_cast<const float4*>(bows + (size_t)b*VV + v0);
                wv[0] = w4.x; wv[1] = w4.y; wv[2] = w4.z; wv[3] = w4.w;
            } else {
                #pragma unroll
                for (int j = 0; j < 4; j++) if (v0 + j < VV) wv[j] = bows[(size_t)b*VV + v0 + j];
            }
            if constexpr (EPI == 1) {
                float inv = g_invn[b];
                #pragma unroll
                for (int j = 0; j < 4; j++) {
                    if (v0 + j < VV && wv[j] != 0.f)
                        local += __fdividef(wv[j] * inv, acc[i][j] + 1e-30f);
                }
            } else {
                #pragma unroll
                for (int j = 0; j < 4; j++) {
                    if (v0 + j >= VV) continue;
                    float r = acc[i][j];
                    float w = wv[j];
                    if (w == 0.f) { local += r; }
                    else {
                        int ib = (int)w;
                        float lg = (ib >= 0 && ib < 5 && (float)ib == w) ? c_lg[ib] : lgammaf(w + 1.f);
                        local += r + lg - w * __logf(r + 1e-10f);
                    }
                }
            }
        }
        __shared__ float red[256];
        red[tid] = local; __syncthreads();
        for (int s = 128; s > 0; s >>= 1) { if (tid < s) red[tid] += red[tid+s]; __syncthreads(); }
        if (tid == 0) {
            float* dst = (EPI == 1) ? g_partF : g_partT;
            dst[blockIdx.y * gridDim.x + blockIdx.x] = red[0];
        }
    }
}

// ---------------- phi denominators S_k = sum_v dis[v,k] ----------------
__global__ void k_spart() {
    int t = threadIdx.x;
    if (t >= KK) return;
    int v0 = blockIdx.x * 500;
    float s = 0.f;
    for (int v = v0; v < v0 + 500; v++) s += g_dis[(size_t)v*KK + t];
    g_Spart[blockIdx.x*KK + t] = s;
}
__global__ void k_sreduce() {
    int t = threadIdx.x;
    if (t < KK) {
        float s = 0.f;
        for (int i = 0; i < 100; i++) s += g_Spart[i*KK + t];
        g_S[t] = s;
    }
}
__global__ void k_theta2() {
    int idx = blockIdx.x * 256 + threadIdx.x;
    if (idx >= BN_*KK) return;
    g_theta2[idx] = g_theta[idx] / g_S[idx % KK];
}

// ---------------- backward cost per doc ----------------
__global__ void k_bwd() {
    int b = blockIdx.x, t = threadIdx.x;
    float local = 0.f;
    if (t < KK) {
        float cs = g_colsum[(size_t)b*KK + t];
        local = g_ntok[b] * g_tn[(size_t)b*KK + t] / (cs + 1e-30f);
    }
    __shared__ float red[256];
    red[t] = local; __syncthreads();
    for (int s = 128; s > 0; s >>= 1) { if (t < s) red[t] += red[t+s]; __syncthreads(); }
    if (t == 0) g_partB[b] = red[0];
}

// ---------------- final deterministic reductions + scaling ----------------
__global__ void k_final(float* __restrict__ out) {
    int t = threadIdx.x;
    __shared__ double red[256];

    double s = 0.0;
    for (int i = t; i < NPART; i += 256) s += (double)g_partF[i];
    red[t] = s; __syncthreads();
    for (int st = 128; st > 0; st >>= 1) { if (t < st) red[t] += red[t+st]; __syncthreads(); }
    double fwd = red[0]; __syncthreads();

    s = 0.0;
    for (int i = t; i < NPART; i += 256) s += (double)g_partT[i];
    red[t] = s; __syncthreads();
    for (int st = 128; st > 0; st >>= 1) { if (t < st) red[t] += red[t+st]; __syncthreads(); }
    double tmsum = red[0]; __syncthreads();

    s = 0.0;
    for (int i = t; i < BN_; i += 256) s += (double)g_partB[i];
    red[t] = s; __syncthreads();
    for (int st = 128; st > 0; st >>= 1) { if (t < st) red[t] += red[t+st]; __syncthreads(); }
    double bwd = red[0];

    if (t == 0) {
        out[0] = (float)(1.0 * (tmsum / (double)BN_));   // EPSILON * tm
        out[1] = (float)(0.5 * fwd);                     // BETA * forward
        out[2] = (float)(0.5 * bwd);                     // (1-BETA) * backward
    }
}

// ---------------- launch ----------------
extern "C" void kernel_launch(void* const* d_in, const int* in_sizes, int n_in,
                              void* d_out, int out_size) {
    const float* bows  = (const float*)d_in[0];
    const float* rho   = (const float*)d_in[1];
    const float* alpha = (const float*)d_in[2];
    const float* W1    = (const float*)d_in[3];
    const float* b1    = (const float*)d_in[4];
    const float* W2    = (const float*)d_in[5];
    const float* b2    = (const float*)d_in[6];
    float* out = (float*)d_out;

    // doc token counts
    k_ntok<<<BN_, 256>>>(bows);

    // hid = relu(bows@W1 + b1)   (split-K 6)
    gemm_ab<0><<<dim3(13, 8, K1_SPLIT), 256>>>(bows, W1);
    k1_reduce<<<(BN_*HIDD)/256, 256>>>(b1);

    // theta, theta_norm
    k_theta<<<BN_, 256>>>(W2, b2);

    // dis = clip(exp(rho@alpha^T))
    gemm_abt<0><<<dim3(4, VT), 256>>>(rho, alpha, nullptr);

    // S_k, theta2 = theta / S
    k_spart<<<100, 256>>>();
    k_sreduce<<<1, 256>>>();
    k_theta2<<<(BN_*KK + 255)/256, 256>>>();

    // colsum = bows@dis   (split-K 24)
    gemm_ab<1><<<dim3(4, 8, K4_SPLIT), 256>>>(bows, nullptr);
    k4_reduce<<<(BN_*KK + 255)/256, 256>>>();

    // backward cost partials
    k_bwd<<<BN_, 256>>>();

    // forward cost: den = tn@dis^T fused reduction
    gemm_abt<1><<<dim3(VT, 8), 256>>>(nullptr, nullptr, bows);

    // tm cost: recon = theta2@dis^T fused Poisson reduction
    gemm_abt<2><<<dim3(VT, 8), 256>>>(nullptr, nullptr, bows);

    // final scalars
    k_final<<<1, 256>>>(out);
}

// round 4
// speedup vs baseline: 4.6449x; 4.6449x over previous
#include <cuda_runtime.h>
#include <cuda_bf16.h>
#include <math.h>
#include <stdint.h>

#define BN 512
#define VV 50000
#define KK 200
#define HH 300
#define HIDD 800
#define VP 50048
#define KP 256
#define HP 320
#define NH 896
#define Z1 16
#define Z2 32
#define NKT (VP/32)            // 1564 k-tiles over vocab
#define MT ((VV+127)/128)      // 391
#define NPART (MT*4)

// ---------------- scratch ----------------
__device__ __align__(16) __nv_bfloat16 g_bows16[(size_t)BN*VP];
__device__ __align__(16) __nv_bfloat16 g_w1t[(size_t)NH*VP];
__device__ __align__(16) __nv_bfloat16 g_rho16[(size_t)VV*HP];
__device__ __align__(16) __nv_bfloat16 g_al16[(size_t)KP*HP];
__device__ __align__(16) __nv_bfloat16 g_dis16[(size_t)VV*KP];
__device__ __align__(16) __nv_bfloat16 g_disT16[(size_t)KP*VP];
__device__ __align__(16) __nv_bfloat16 g_tn16[(size_t)BN*KP];
__device__ __align__(16) __nv_bfloat16 g_th216[(size_t)BN*KP];
__device__ float g_p1[(size_t)Z1*BN*NH];
__device__ float g_p2[(size_t)Z2*BN*KP];
__device__ float g_hid[BN*HIDD];
__device__ float g_theta[BN*KK];
__device__ float g_tn[BN*KK];
__device__ float g_ntok[BN];
__device__ float g_invn[BN];
__device__ float g_S[KP];
__device__ float g_Sp[MT*KP];
__device__ float g_colsum[BN*KK];
__device__ float g_pF[NPART];
__device__ float g_pT[NPART];
__device__ float g_pB[BN];

__constant__ float c_lg[5] = {0.0f, 0.0f, 0.69314718055994531f,
                              1.79175946922805500f, 3.17805383034794562f};

// ---------------- helpers ----------------
__device__ __forceinline__ uint32_t s2u(const void* p) {
    uint32_t a;
    asm("{ .reg .u64 t; cvta.to.shared.u64 t, %1; cvt.u32.u64 %0, t; }" : "=r"(a) : "l"(p));
    return a;
}
__device__ __forceinline__ void cpa(uint32_t sa, const void* ga, int sz) {
    asm volatile("cp.async.cg.shared.global [%0], [%1], 16, %2;"
                 :: "r"(sa), "l"(ga), "r"(sz) : "memory");
}
#define CPCOMMIT() asm volatile("cp.async.commit_group;" ::: "memory")
#define CPWAIT(n)  asm volatile("cp.async.wait_group %0;" :: "n"(n) : "memory")
#define LDSM4(r, a) \
    asm volatile("ldmatrix.sync.aligned.m8n8.x4.shared.b16 {%0,%1,%2,%3}, [%4];" \
        : "=r"((r)[0]), "=r"((r)[1]), "=r"((r)[2]), "=r"((r)[3]) : "r"(a))

__device__ __forceinline__ void mma16816(float* c, const uint32_t* a, uint32_t b0, uint32_t b1) {
    asm volatile("mma.sync.aligned.m16n8k16.row.col.f32.bf16.bf16.f32 "
        "{%0,%1,%2,%3}, {%4,%5,%6,%7}, {%8,%9}, {%0,%1,%2,%3};"
        : "+f"(c[0]), "+f"(c[1]), "+f"(c[2]), "+f"(c[3])
        : "r"(a[0]), "r"(a[1]), "r"(a[2]), "r"(a[3]), "r"(b0), "r"(b1));
}
__device__ __forceinline__ void unp2(uint32_t u, float& a, float& b) {
    __nv_bfloat162 t = *reinterpret_cast<__nv_bfloat162*>(&u);
    a = __bfloat162float(t.x); b = __bfloat162float(t.y);
}
__device__ __forceinline__ uint32_t pk2(float a, float b) {
    return ((uint32_t)__bfloat16_as_ushort(__float2bfloat16_rn(b)) << 16) |
            (uint32_t)__bfloat16_as_ushort(__float2bfloat16_rn(a));
}

// smem tile layout: 128 rows x 32 bf16, row pitch 80 bytes (conflict-free ldmatrix)
#define PITCH 80
#define TILEB (128*PITCH)      // 10240
#define STAGEB (2*TILEB)       // 20480  (A then B)

// ---------------- bf16 HMMA GEMM: C[M,N] = A[M,K] @ B[N,K]^T ----------------
// EPI0: dis = clip(exp(rho@al^T))                 M=VV   N=KP(2)  K=HP
// EPI1: p1[z] = bows@w1t^T                        M=512  N=NH(7)  K=VP splitZ1
// EPI2: p2[z] = bows@disT^T                       M=512  N=KP(2)  K=VP splitZ2
// EPI3: den = tn@dis^T + fused forward reduce     M=512  N=VV     K=KP
// EPI4: recon = th2@dis^T + fused Poisson reduce  M=512  N=VV     K=KP
template<int EPI>
__global__ void __launch_bounds__(256) mm() {
    __shared__ __align__(16) char smem[2*STAGEB];
    const uint32_t sb = s2u(smem);
    const int tid = threadIdx.x, lane = tid & 31, wid = tid >> 5;
    const int wm = (wid & 3) * 32, wn = (wid >> 2) * 64;
    const int m0 = blockIdx.x * 128, n0 = blockIdx.y * 128;

    const __nv_bfloat16 *A, *B;
    int lda, ldb, kt0, ktn;
    bool azf = false, bzf = false;
    if (EPI == 0) { A = g_rho16; B = g_al16; lda = HP; ldb = HP; kt0 = 0; ktn = HP/32; azf = true; }
    else if (EPI == 1) { A = g_bows16; B = g_w1t; lda = VP; ldb = VP;
                         kt0 = blockIdx.z * 98; ktn = min(kt0 + 98, NKT) - kt0; }
    else if (EPI == 2) { A = g_bows16; B = g_disT16; lda = VP; ldb = VP;
                         kt0 = blockIdx.z * 49; ktn = min(kt0 + 49, NKT) - kt0; }
    else { A = (EPI == 3) ? g_tn16 : g_th216; B = g_dis16; lda = KP; ldb = KP;
           kt0 = 0; ktn = KP/32; bzf = true; }

    auto issue = [&](int it) {
        const int k0 = (kt0 + it) * 32;
        const uint32_t st = sb + (it & 1) * STAGEB;
        #pragma unroll
        for (int i = 0; i < 2; i++) {
            int idx = i * 256 + tid;
            int r = idx >> 2, c = idx & 3;
            int ar = m0 + r;
            bool av = (!azf) || (ar < VV);
            cpa(st + r*PITCH + c*16,
                A + (size_t)(av ? ar : 0)*lda + k0 + c*8, av ? 16 : 0);
            int br = n0 + r;
            bool bv = (!bzf) || (br < VV);
            cpa(st + TILEB + r*PITCH + c*16,
                B + (size_t)(bv ? br : 0)*ldb + k0 + c*8, bv ? 16 : 0);
        }
        CPCOMMIT();
    };

    float acc[2][8][4];
    #pragma unroll
    for (int mi = 0; mi < 2; mi++)
        #pragma unroll
        for (int ni = 0; ni < 8; ni++)
            #pragma unroll
            for (int q = 0; q < 4; q++) acc[mi][ni][q] = 0.f;

    issue(0);
    if (ktn > 1) issue(1);

    for (int it = 0; it < ktn; ++it) {
        if (it == ktn - 1) { CPWAIT(0); } else { CPWAIT(1); }
        __syncthreads();
        const uint32_t st = sb + (it & 1) * STAGEB;
        #pragma unroll
        for (int ks = 0; ks < 2; ks++) {
            uint32_t af[2][4], bfm[4][4];
            #pragma unroll
            for (int mi = 0; mi < 2; mi++) {
                int row = wm + mi*16 + (lane & 15);
                uint32_t ad = st + row*PITCH + (ks*2 + (lane >> 4))*16;
                LDSM4(af[mi], ad);
            }
            #pragma unroll
            for (int nj = 0; nj < 4; nj++) {
                int row = wn + nj*16 + (lane & 15);
                uint32_t ad = st + TILEB + row*PITCH + (ks*2 + (lane >> 4))*16;
                LDSM4(bfm[nj], ad);
            }
            #pragma unroll
            for (int mi = 0; mi < 2; mi++)
                #pragma unroll
                for (int nj = 0; nj < 4; nj++) {
                    mma16816(acc[mi][nj*2],   af[mi], bfm[nj][0], bfm[nj][2]);
                    mma16816(acc[mi][nj*2+1], af[mi], bfm[nj][1], bfm[nj][3]);
                }
        }
        __syncthreads();
        if (it + 2 < ktn) issue(it + 2);
    }

    const int rq = lane >> 2, cq = (lane & 3) * 2;

    if constexpr (EPI == 0) {
        #pragma unroll
        for (int mi = 0; mi < 2; mi++)
            #pragma unroll
            for (int h = 0; h < 2; h++) {
                int row = m0 + wm + mi*16 + rq + h*8;
                if (row >= VV) continue;
                #pragma unroll
                for (int ni = 0; ni < 8; ni++) {
                    int col = n0 + wn + ni*8 + cq;
                    float e0 = fminf(fmaxf(expf(acc[mi][ni][2*h]),   1e-30f), 1e10f);
                    float e1 = fminf(fmaxf(expf(acc[mi][ni][2*h+1]), 1e-30f), 1e10f);
                    *reinterpret_cast<uint32_t*>(g_dis16 + (size_t)row*KP + col) = pk2(e0, e1);
                }
            }
    } else if constexpr (EPI == 1 || EPI == 2) {
        constexpr int LDN = (EPI == 1) ? NH : KP;
        float* dst = ((EPI == 1) ? g_p1 : g_p2) + (size_t)blockIdx.z * BN * LDN;
        #pragma unroll
        for (int mi = 0; mi < 2; mi++)
            #pragma unroll
            for (int h = 0; h < 2; h++) {
                int row = m0 + wm + mi*16 + rq + h*8;
                #pragma unroll
                for (int ni = 0; ni < 8; ni++) {
                    int col = n0 + wn + ni*8 + cq;
                    float2 v = make_float2(acc[mi][ni][2*h], acc[mi][ni][2*h+1]);
                    *reinterpret_cast<float2*>(dst + (size_t)row*LDN + col) = v;
                }
            }
    } else {
        float nacc = 0.f;
        #pragma unroll
        for (int mi = 0; mi < 2; mi++)
            #pragma unroll
            for (int h = 0; h < 2; h++) {
                int b = m0 + wm + mi*16 + rq + h*8;
                float inv = (EPI == 3) ? g_invn[b] : 0.f;
                #pragma unroll
                for (int ni = 0; ni < 8; ni++) {
                    int v = n0 + wn + ni*8 + cq;
                    uint32_t wp = *reinterpret_cast<const uint32_t*>(g_bows16 + (size_t)b*VP + v);
                    float w0, w1; unp2(wp, w0, w1);
                    float d0 = acc[mi][ni][2*h], d1 = acc[mi][ni][2*h+1];
                    if (EPI == 3) {
                        if (w0 != 0.f) nacc += __fdividef(w0 * inv, d0 + 1e-30f);
                        if (w1 != 0.f) nacc += __fdividef(w1 * inv, d1 + 1e-30f);
                    } else {
                        if (w0 == 0.f) nacc += d0;
                        else nacc += d0 + c_lg[(int)w0] - w0 * __logf(d0 + 1e-10f);
                        if (w1 == 0.f) nacc += d1;
                        else nacc += d1 + c_lg[(int)w1] - w1 * __logf(d1 + 1e-10f);
                    }
                }
            }
        __syncthreads();
        float* red = (float*)smem;
        red[tid] = nacc; __syncthreads();
        for (int s = 128; s > 0; s >>= 1) { if (tid < s) red[tid] += red[tid+s]; __syncthreads(); }
        if (tid == 0) {
            float* dst = (EPI == 3) ? g_pF : g_pT;
            dst[blockIdx.y*4 + blockIdx.x] = red[0];
        }
    }
}

// ---------------- converters ----------------
__global__ void k_cvt_bows(const float* __restrict__ bows) {
    int b = blockIdx.x, tid = threadIdx.x;
    float s = 0.f;
    for (int i = tid; i < VP/8; i += 256) {
        int v = i * 8;
        uint4 o = make_uint4(0u,0u,0u,0u);
        if (v < VV) {
            const float4* p = reinterpret_cast<const float4*>(bows + (size_t)b*VV + v);
            float4 a = p[0], c = p[1];
            s += a.x+a.y+a.z+a.w + c.x+c.y+c.z+c.w;
            o.x = pk2(a.x,a.y); o.y = pk2(a.z,a.w); o.z = pk2(c.x,c.y); o.w = pk2(c.z,c.w);
        }
        reinterpret_cast<uint4*>(g_bows16)[(size_t)b*(VP/8) + i] = o;
    }
    __shared__ float red[256];
    red[tid] = s; __syncthreads();
    for (int st = 128; st > 0; st >>= 1) { if (tid < st) red[tid] += red[tid+st]; __syncthreads(); }
    if (tid == 0) { float n = red[0]; g_ntok[b] = n; g_invn[b] = (n > 0.f) ? 1.f/n : 0.f; }
}
__global__ void k_cvt_w1t(const float* __restrict__ W1) {
    __shared__ float t[32][33];
    int tx = threadIdx.x, ty = threadIdx.y;
    int v0 = blockIdx.x*32, h0 = blockIdx.y*32;
    #pragma unroll
    for (int i = 0; i < 4; i++) {
        int r = ty + i*8;
        t[r][tx] = (v0+r < VV && h0+tx < HIDD) ? W1[(size_t)(v0+r)*HIDD + h0+tx] : 0.f;
    }
    __syncthreads();
    #pragma unroll
    for (int i = 0; i < 4; i++) {
        int r = ty + i*8;
        g_w1t[(size_t)(h0+r)*VP + v0+tx] = __float2bfloat16_rn(t[tx][r]);
    }
}
__global__ void k_cvt_rho(const float* __restrict__ rho) {
    int idx = blockIdx.x*256 + threadIdx.x;
    if (idx >= VV*HP) return;
    int r = idx / HP, c = idx % HP;
    g_rho16[idx] = (c < HH) ? __float2bfloat16_rn(rho[(size_t)r*HH + c]) : __nv_bfloat16(0.f);
}
__global__ void k_cvt_al(const float* __restrict__ al) {
    int idx = blockIdx.x*256 + threadIdx.x;
    if (idx >= KP*HP) return;
    int r = idx / HP, c = idx % HP;
    g_al16[idx] = (r < KK && c < HH) ? __float2bfloat16_rn(al[(size_t)r*HH + c]) : __nv_bfloat16(0.f);
}
__global__ void k_trans() {
    __shared__ __nv_bfloat16 t[32][33];
    int tx = threadIdx.x, ty = threadIdx.y;
    int k0 = blockIdx.x*32, v0 = blockIdx.y*32;
    #pragma unroll
    for (int i = 0; i < 4; i++) {
        int r = ty + i*8;
        t[r][tx] = (v0+r < VV) ? g_dis16[(size_t)(v0+r)*KP + k0+tx] : __nv_bfloat16(0.f);
    }
    __syncthreads();
    #pragma unroll
    for (int i = 0; i < 4; i++) {
        int r = ty + i*8;
        g_disT16[(size_t)(k0+r)*VP + v0+tx] = t[tx][r];
    }
}

// ---------------- small kernels ----------------
__global__ void k_sp() {
    int i = blockIdx.x, t = threadIdx.x;
    int r0 = i*128, r1 = min(r0+128, VV);
    float s = 0.f;
    for (int r = r0; r < r1; r++) s += __bfloat162float(g_dis16[(size_t)r*KP + t]);
    g_Sp[i*KP + t] = s;
}
__global__ void k_sr() {
    int t = threadIdx.x;
    float s = 0.f;
    for (int i = 0; i < MT; i++) s += g_Sp[i*KP + t];
    g_S[t] = s;
}
__global__ void k1_reduce(const float* __restrict__ b1) {
    int idx = blockIdx.x*256 + threadIdx.x;
    if (idx >= BN*HIDD) return;
    int b = idx / HIDD, h = idx % HIDD;
    float s = 0.f;
    #pragma unroll
    for (int z = 0; z < Z1; z++) s += g_p1[(size_t)z*BN*NH + (size_t)b*NH + h];
    g_hid[idx] = fmaxf(s + b1[h], 0.f);
}
__global__ void k4_reduce() {
    int idx = blockIdx.x*256 + threadIdx.x;
    if (idx >= BN*KK) return;
    int b = idx / KK, k = idx % KK;
    float s = 0.f;
    #pragma unroll
    for (int z = 0; z < Z2; z++) s += g_p2[(size_t)z*BN*KP + (size_t)b*KP + k];
    g_colsum[idx] = s;
}
__global__ void k_mlp2(const float* __restrict__ W2, const float* __restrict__ b2) {
    __shared__ __align__(16) float As[16][68];
    __shared__ __align__(16) float Bs[16][68];
    const int tid = threadIdx.x, tx = tid & 15, ty = tid >> 4;
    const int m0 = blockIdx.y*64, n0 = blockIdx.x*64;
    const int ar = tid >> 2, ac = (tid & 3) << 2;
    const int br = tid >> 4, bc = (tid & 15) << 2;
    float acc[4][4];
    #pragma unroll
    for (int i = 0; i < 4; i++)
        #pragma unroll
        for (int j = 0; j < 4; j++) acc[i][j] = 0.f;
    for (int kt = 0; kt < 50; ++kt) {
        int k0 = kt*16;
        float4 va = *reinterpret_cast<const float4*>(g_hid + (size_t)(m0+ar)*HIDD + k0 + ac);
        As[ac+0][ar] = va.x; As[ac+1][ar] = va.y; As[ac+2][ar] = va.z; As[ac+3][ar] = va.w;
        float4 vb = make_float4(0.f,0.f,0.f,0.f);
        int gn = n0 + bc;
        const float* bp = W2 + (size_t)(k0+br)*KK + gn;
        if (gn + 3 < KK) vb = *reinterpret_cast<const float4*>(bp);
        else { if (gn<KK) vb.x=bp[0]; if (gn+1<KK) vb.y=bp[1]; if (gn+2<KK) vb.z=bp[2]; }
        *reinterpret_cast<float4*>(&Bs[br][bc]) = vb;
        __syncthreads();
        #pragma unroll
        for (int k = 0; k < 16; k++) {
            float4 a = *reinterpret_cast<const float4*>(&As[k][ty << 2]);
            float4 b = *reinterpret_cast<const float4*>(&Bs[k][tx << 2]);
            float av[4] = {a.x,a.y,a.z,a.w}, bv[4] = {b.x,b.y,b.z,b.w};
            #pragma unroll
            for (int i = 0; i < 4; i++)
                #pragma unroll
                for (int j = 0; j < 4; j++) acc[i][j] = fmaf(av[i], bv[j], acc[i][j]);
        }
        __syncthreads();
    }
    #pragma unroll
    for (int i = 0; i < 4; i++) {
        int m = m0 + (ty << 2) + i;
        #pragma unroll
        for (int j = 0; j < 4; j++) {
            int n = n0 + (tx << 2) + j;
            if (n < KK) {
                float x = acc[i][j] + b2[n];
                g_theta[(size_t)m*KK + n] = fmaxf(x, 0.f) + log1pf(expf(-fabsf(x)));
            }
        }
    }
}
__global__ void k_softmax() {
    int b = blockIdx.x, t = threadIdx.x;
    __shared__ float red[256];
    float th = (t < KK) ? g_theta[(size_t)b*KK + t] : -1e30f;
    red[t] = th; __syncthreads();
    for (int s = 128; s > 0; s >>= 1) { if (t < s) red[t] = fmaxf(red[t], red[t+s]); __syncthreads(); }
    float mx = red[0]; __syncthreads();
    float e = (t < KK) ? expf(th - mx) : 0.f;
    red[t] = e; __syncthreads();
    for (int s = 128; s > 0; s >>= 1) { if (t < s) red[t] += red[t+s]; __syncthreads(); }
    float tn = e / red[0];
    if (t < KK) g_tn[(size_t)b*KK + t] = tn;
    g_tn16[(size_t)b*KP + t] = (t < KK) ? __float2bfloat16_rn(tn) : __nv_bfloat16(0.f);
}
__global__ void k_th2() {
    int idx = blockIdx.x*256 + threadIdx.x;
    int b = idx >> 8, k = idx & 255;
    g_th216[idx] = (k < KK) ? __float2bfloat16_rn(g_theta[(size_t)b*KK + k] / g_S[k])
                            : __nv_bfloat16(0.f);
}
__global__ void k_bwd() {
    int b = blockIdx.x, t = threadIdx.x;
    float local = 0.f;
    if (t < KK)
        local = g_ntok[b] * g_tn[(size_t)b*KK + t] / (g_colsum[(size_t)b*KK + t] + 1e-30f);
    __shared__ float red[256];
    red[t] = local; __syncthreads();
    for (int s = 128; s > 0; s >>= 1) { if (t < s) red[t] += red[t+s]; __syncthreads(); }
    if (t == 0) g_pB[b] = red[0];
}
__global__ void k_final(float* __restrict__ out) {
    int t = threadIdx.x;
    __shared__ double red[256];
    double s = 0.0;
    for (int i = t; i < NPART; i += 256) s += (double)g_pF[i];
    red[t] = s; __syncthreads();
    for (int st = 128; st > 0; st >>= 1) { if (t < st) red[t] += red[t+st]; __syncthreads(); }
    double fwd = red[0]; __syncthreads();
    s = 0.0;
    for (int i = t; i < NPART; i += 256) s += (double)g_pT[i];
    red[t] = s; __syncthreads();
    for (int st = 128; st > 0; st >>= 1) { if (t < st) red[t] += red[t+st]; __syncthreads(); }
    double tm = red[0]; __syncthreads();
    s = 0.0;
    for (int i = t; i < BN; i += 256) s += (double)g_pB[i];
    red[t] = s; __syncthreads();
    for (int st = 128; st > 0; st >>= 1) { if (t < st) red[t] += red[t+st]; __syncthreads(); }
    double bwd = red[0];
    if (t == 0) {
        out[0] = (float)(tm / (double)BN);
        out[1] = (float)(0.5 * fwd);
        out[2] = (float)(0.5 * bwd);
    }
}

// ---------------- launch ----------------
extern "C" void kernel_launch(void* const* d_in, const int* in_sizes, int n_in,
                              void* d_out, int out_size) {
    const float* bows  = (const float*)d_in[0];
    const float* rho   = (const float*)d_in[1];
    const float* alpha = (const float*)d_in[2];
    const float* W1    = (const float*)d_in[3];
    const float* b1    = (const float*)d_in[4];
    const float* W2    = (const float*)d_in[5];
    const float* b2    = (const float*)d_in[6];
    float* out = (float*)d_out;

    // conversions (+fused ntok)
    k_cvt_bows<<<BN, 256>>>(bows);
    k_cvt_w1t<<<dim3((VP+31)/32, (NH+31)/32), dim3(32, 8)>>>(W1);
    k_cvt_rho<<<(VV*HP + 255)/256, 256>>>(rho);
    k_cvt_al<<<(KP*HP + 255)/256, 256>>>(alpha);

    // dis = clip(exp(rho@alpha^T)), then S_k and disT
    mm<0><<<dim3(MT, 2), 256>>>();
    k_sp<<<MT, KP>>>();
    k_sr<<<1, KP>>>();
    k_trans<<<dim3(KP/32, VP/32), dim3(32, 8)>>>();

    // hid = relu(bows@W1 + b1); theta; softmax; theta2
    mm<1><<<dim3(4, 7, Z1), 256>>>();
    k1_reduce<<<(BN*HIDD + 255)/256, 256>>>(b1);
    k_mlp2<<<dim3(4, 8), 256>>>(W2, b2);
    k_softmax<<<BN, 256>>>();
    k_th2<<<(BN*KP)/256, 256>>>();

    // colsum = bows@dis; backward
    mm<2><<<dim3(4, 2, Z2), 256>>>();
    k4_reduce<<<(BN*KK + 255)/256, 256>>>();
    k_bwd<<<BN, 256>>>();

    // den + forward;  recon + Poisson
    mm<3><<<dim3(4, MT), 256>>>();
    mm<4><<<dim3(4, MT), 256>>>();

    k_final<<<1, 256>>>(out);
}

// round 5
// speedup vs baseline: 4.9220x; 1.0597x over previous
#include <cuda_runtime.h>
#include <cuda_bf16.h>
#include <math.h>
#include <stdint.h>

#define BN 512
#define VV 50000
#define KK 200
#define HH 300
#define HIDD 800
#define VP 50048
#define KP 256
#define HP 320
#define NH 896
#define Z1 16
#define Z2 32
#define NKT (VP/32)            // 1564 k-tiles over vocab
#define MT ((VV+127)/128)      // 391 (m-tiles for mm0)
#define NT64 (VP/64)           // 782 (n-tiles for mm34)
#define NP2 (NT64*4)           // 3128 partials

// ---------------- scratch ----------------
__device__ __align__(16) __nv_bfloat16 g_bows16[(size_t)BN*VP];
__device__ __align__(16) __nv_bfloat16 g_w1t[(size_t)NH*VP];
__device__ __align__(16) __nv_bfloat16 g_rho16[(size_t)VV*HP];
__device__ __align__(16) __nv_bfloat16 g_al16[(size_t)KP*HP];
__device__ __align__(16) __nv_bfloat16 g_dis16[(size_t)VV*KP];
__device__ __align__(16) __nv_bfloat16 g_disT16[(size_t)KP*VP];
__device__ __align__(16) __nv_bfloat16 g_tn16[(size_t)BN*KP];
__device__ __align__(16) __nv_bfloat16 g_th216[(size_t)BN*KP];
__device__ float g_p1[(size_t)Z1*BN*NH];
__device__ float g_p2[(size_t)Z2*BN*KP];
__device__ float g_hid[BN*HIDD];
__device__ float g_theta[BN*KK];
__device__ float g_tn[BN*KK];
__device__ float g_ntok[BN];
__device__ float g_invn[BN];
__device__ float g_S[KP];
__device__ float g_Sp[MT*KP];
__device__ float g_pF[NP2];
__device__ float g_pT[NP2];
__device__ float g_pB[BN];

__constant__ float c_lg[5] = {0.0f, 0.0f, 0.69314718055994531f,
                              1.79175946922805500f, 3.17805383034794562f};

// ---------------- helpers ----------------
__device__ __forceinline__ uint32_t s2u(const void* p) {
    uint32_t a;
    asm("{ .reg .u64 t; cvta.to.shared.u64 t, %1; cvt.u32.u64 %0, t; }" : "=r"(a) : "l"(p));
    return a;
}
__device__ __forceinline__ void cpa(uint32_t sa, const void* ga, int sz) {
    asm volatile("cp.async.cg.shared.global [%0], [%1], 16, %2;"
                 :: "r"(sa), "l"(ga), "r"(sz) : "memory");
}
#define CPCOMMIT() asm volatile("cp.async.commit_group;" ::: "memory")
#define CPWAIT(n)  asm volatile("cp.async.wait_group %0;" :: "n"(n) : "memory")
#define LDSM4(r, a) \
    asm volatile("ldmatrix.sync.aligned.m8n8.x4.shared.b16 {%0,%1,%2,%3}, [%4];" \
        : "=r"((r)[0]), "=r"((r)[1]), "=r"((r)[2]), "=r"((r)[3]) : "r"(a))

__device__ __forceinline__ void mma16816(float* c, const uint32_t* a, uint32_t b0, uint32_t b1) {
    asm volatile("mma.sync.aligned.m16n8k16.row.col.f32.bf16.bf16.f32 "
        "{%0,%1,%2,%3}, {%4,%5,%6,%7}, {%8,%9}, {%0,%1,%2,%3};"
        : "+f"(c[0]), "+f"(c[1]), "+f"(c[2]), "+f"(c[3])
        : "r"(a[0]), "r"(a[1]), "r"(a[2]), "r"(a[3]), "r"(b0), "r"(b1));
}
__device__ __forceinline__ void unp2(uint32_t u, float& a, float& b) {
    __nv_bfloat162 t = *reinterpret_cast<__nv_bfloat162*>(&u);
    a = __bfloat162float(t.x); b = __bfloat162float(t.y);
}
__device__ __forceinline__ uint32_t pk2(float a, float b) {
    return ((uint32_t)__bfloat16_as_ushort(__float2bfloat16_rn(b)) << 16) |
            (uint32_t)__bfloat16_as_ushort(__float2bfloat16_rn(a));
}

#define PITCH 80
#define TILEB (128*PITCH)      // 10240
#define STAGEB (2*TILEB)       // 20480

// ---------------- bf16 HMMA GEMM template: C[M,N] = A[M,K] @ B[N,K]^T ----------------
// EPI0: dis = clip(exp(rho@al^T)) + fused S partials + fused disT transpose
// EPI1: p1[z] = bows@w1t^T   split-K Z1
// EPI2: p2[z] = bows@disT^T  split-K Z2
template<int EPI>
__global__ void __launch_bounds__(256) mm() {
    __shared__ __align__(16) char smem[2*STAGEB];
    const uint32_t sb = s2u(smem);
    const int tid = threadIdx.x, lane = tid & 31, wid = tid >> 5;
    const int wm = (wid & 3) * 32, wn = (wid >> 2) * 64;
    const int m0 = blockIdx.x * 128, n0 = blockIdx.y * 128;

    const __nv_bfloat16 *A, *B;
    int lda, ldb, kt0, ktn;
    bool azf = false;
    if (EPI == 0) { A = g_rho16; B = g_al16; lda = HP; ldb = HP; kt0 = 0; ktn = HP/32; azf = true; }
    else if (EPI == 1) { A = g_bows16; B = g_w1t; lda = VP; ldb = VP;
                         kt0 = blockIdx.z * 98; ktn = min(kt0 + 98, NKT) - kt0; }
    else { A = g_bows16; B = g_disT16; lda = VP; ldb = VP;
           kt0 = blockIdx.z * 49; ktn = min(kt0 + 49, NKT) - kt0; }

    auto issue = [&](int it) {
        const int k0 = (kt0 + it) * 32;
        const uint32_t st = sb + (it & 1) * STAGEB;
        #pragma unroll
        for (int i = 0; i < 2; i++) {
            int idx = i * 256 + tid;
            int r = idx >> 2, c = idx & 3;
            int ar = m0 + r;
            bool av = (!azf) || (ar < VV);
            cpa(st + r*PITCH + c*16, A + (size_t)(av ? ar : 0)*lda + k0 + c*8, av ? 16 : 0);
            cpa(st + TILEB + r*PITCH + c*16, B + (size_t)(n0 + r)*ldb + k0 + c*8, 16);
        }
        CPCOMMIT();
    };

    float acc[2][8][4];
    #pragma unroll
    for (int mi = 0; mi < 2; mi++)
        #pragma unroll
        for (int ni = 0; ni < 8; ni++)
            #pragma unroll
            for (int q = 0; q < 4; q++) acc[mi][ni][q] = 0.f;

    issue(0);
    if (ktn > 1) issue(1);

    for (int it = 0; it < ktn; ++it) {
        if (it == ktn - 1) { CPWAIT(0); } else { CPWAIT(1); }
        __syncthreads();
        const uint32_t st = sb + (it & 1) * STAGEB;
        #pragma unroll
        for (int ks = 0; ks < 2; ks++) {
            uint32_t af[2][4], bfm[4][4];
            #pragma unroll
            for (int mi = 0; mi < 2; mi++) {
                int row = wm + mi*16 + (lane & 15);
                LDSM4(af[mi], st + row*PITCH + (ks*2 + (lane >> 4))*16);
            }
            #pragma unroll
            for (int nj = 0; nj < 4; nj++) {
                int row = wn + nj*16 + (lane & 15);
                LDSM4(bfm[nj], st + TILEB + row*PITCH + (ks*2 + (lane >> 4))*16);
            }
            #pragma unroll
            for (int mi = 0; mi < 2; mi++)
                #pragma unroll
                for (int nj = 0; nj < 4; nj++) {
                    mma16816(acc[mi][nj*2],   af[mi], bfm[nj][0], bfm[nj][2]);
                    mma16816(acc[mi][nj*2+1], af[mi], bfm[nj][1], bfm[nj][3]);
                }
        }
        __syncthreads();
        if (it + 2 < ktn) issue(it + 2);
    }

    const int rq = lane >> 2, cq = (lane & 3) * 2;

    if constexpr (EPI == 0) {
        // stage tile (128 x 128 bf16, pitch 130 elems = 65 words), write dis16 + S partials + disT
        uint32_t* stg = (uint32_t*)smem;
        #pragma unroll
        for (int mi = 0; mi < 2; mi++)
            #pragma unroll
            for (int h = 0; h < 2; h++) {
                int lr = wm + mi*16 + rq + h*8;
                int row = m0 + lr;
                bool rv = row < VV;
                #pragma unroll
                for (int ni = 0; ni < 8; ni++) {
                    int lc = wn + ni*8 + cq;
                    float e0 = rv ? fminf(fmaxf(expf(acc[mi][ni][2*h]),   1e-30f), 1e10f) : 0.f;
                    float e1 = rv ? fminf(fmaxf(expf(acc[mi][ni][2*h+1]), 1e-30f), 1e10f) : 0.f;
                    uint32_t pkd = pk2(e0, e1);
                    stg[lr*65 + (lc >> 1)] = pkd;
                    if (rv) *reinterpret_cast<uint32_t*>(g_dis16 + (size_t)row*KP + n0 + lc) = pkd;
                }
            }
        __syncthreads();
        // column sums over staged tile
        {
            const __nv_bfloat16* sg = (const __nv_bfloat16*)smem;
            int col = tid & 127, half = tid >> 7;
            float s = 0.f;
            #pragma unroll 8
            for (int r = 0; r < 64; r++)
                s += __bfloat162float(sg[(half*64 + r)*130 + col]);
            float* red = (float*)(smem + 33280);
            red[tid] = s;
            __syncthreads();
            if (tid < 128) g_Sp[blockIdx.x*KP + n0 + tid] = red[tid] + red[128 + tid];
        }
        // transposed write (coalesced 4B stores)
        {
            const __nv_bfloat16* sg = (const __nv_bfloat16*)smem;
            #pragma unroll
            for (int i = 0; i < 32; i++) {
                int idx = i*256 + tid;
                int c = idx >> 6, rp = idx & 63;
                __nv_bfloat16 a = sg[(2*rp)*130 + c];
                __nv_bfloat16 b = sg[(2*rp + 1)*130 + c];
                uint32_t val = ((uint32_t)__bfloat16_as_ushort(b) << 16) |
                                (uint32_t)__bfloat16_as_ushort(a);
                *reinterpret_cast<uint32_t*>(g_disT16 + (size_t)(n0 + c)*VP + m0 + 2*rp) = val;
            }
        }
    } else {
        constexpr int LDN = (EPI == 1) ? NH : KP;
        float* dst = ((EPI == 1) ? g_p1 : g_p2) + (size_t)blockIdx.z * BN * LDN;
        #pragma unroll
        for (int mi = 0; mi < 2; mi++)
            #pragma unroll
            for (int h = 0; h < 2; h++) {
                int row = m0 + wm + mi*16 + rq + h*8;
                #pragma unroll
                for (int ni = 0; ni < 8; ni++) {
                    int col = n0 + wn + ni*8 + cq;
                    float2 v = make_float2(acc[mi][ni][2*h], acc[mi][ni][2*h+1]);
                    *reinterpret_cast<float2*>(dst + (size_t)row*LDN + col) = v;
                }
            }
    }
}

// ---------------- merged den+recon kernel (dual accumulator) ----------------
// den = tn@dis^T (forward reduce), recon = th2@dis^T (Poisson reduce); share B tiles.
// block tile 128m x 64n; 256 threads; warps 4(m) x 2(n), warp tile 32x32.
#define STG34 25600
__global__ void __launch_bounds__(256) mm34() {
    extern __shared__ __align__(16) char dsm[];
    const uint32_t sb = s2u(dsm);
    const int tid = threadIdx.x, lane = tid & 31, wid = tid >> 5;
    const int wm = (wid & 3) * 32, wn = (wid >> 2) * 32;
    const int m0 = blockIdx.x * 128, n0 = blockIdx.y * 64;

    auto issue = [&](int it) {
        const int k0 = it * 32;
        const uint32_t st = sb + (it & 1) * STG34;
        #pragma unroll
        for (int i = 0; i < 2; i++) {
            int idx = i * 256 + tid;
            int r = idx >> 2, c = idx & 3;
            cpa(st + r*PITCH + c*16,         g_tn16  + (size_t)(m0 + r)*KP + k0 + c*8, 16);
            cpa(st + 10240 + r*PITCH + c*16, g_th216 + (size_t)(m0 + r)*KP + k0 + c*8, 16);
        }
        {
            int r = tid >> 2, c = tid & 3;     // 64 rows x 4 chunks
            int br = n0 + r;
            bool bv = br < VV;
            cpa(st + 20480 + r*PITCH + c*16, g_dis16 + (size_t)(bv ? br : 0)*KP + k0 + c*8, bv ? 16 : 0);
        }
        CPCOMMIT();
    };

    float a3[2][4][4], a4[2][4][4];
    #pragma unroll
    for (int mi = 0; mi < 2; mi++)
        #pragma unroll
        for (int ni = 0; ni < 4; ni++)
            #pragma unroll
            for (int q = 0; q < 4; q++) { a3[mi][ni][q] = 0.f; a4[mi][ni][q] = 0.f; }

    issue(0); issue(1);
    const int ktn = KP/32;    // 8
    for (int it = 0; it < ktn; ++it) {
        if (it == ktn - 1) { CPWAIT(0); } else { CPWAIT(1); }
        __syncthreads();
        const uint32_t st = sb + (it & 1) * STG34;
        #pragma unroll
        for (int ks = 0; ks < 2; ks++) {
            uint32_t af1[2][4], af2[2][4], bfm[2][4];
            #pragma unroll
            for (int mi = 0; mi < 2; mi++) {
                int row = wm + mi*16 + (lane & 15);
                uint32_t off = row*PITCH + (ks*2 + (lane >> 4))*16;
                LDSM4(af1[mi], st + off);
                LDSM4(af2[mi], st + 10240 + off);
            }
            #pragma unroll
            for (int nj = 0; nj < 2; nj++) {
                int row = wn + nj*16 + (lane & 15);
                LDSM4(bfm[nj], st + 20480 + row*PITCH + (ks*2 + (lane >> 4))*16);
            }
            #pragma unroll
            for (int mi = 0; mi < 2; mi++)
                #pragma unroll
                for (int nj = 0; nj < 2; nj++) {
                    mma16816(a3[mi][nj*2],   af1[mi], bfm[nj][0], bfm[nj][2]);
                    mma16816(a3[mi][nj*2+1], af1[mi], bfm[nj][1], bfm[nj][3]);
                    mma16816(a4[mi][nj*2],   af2[mi], bfm[nj][0], bfm[nj][2]);
                    mma16816(a4[mi][nj*2+1], af2[mi], bfm[nj][1], bfm[nj][3]);
                }
        }
        __syncthreads();
        if (it + 2 < ktn) issue(it + 2);
    }

    const int rq = lane >> 2, cq = (lane & 3) * 2;
    float nF = 0.f, nT = 0.f;
    #pragma unroll
    for (int mi = 0; mi < 2; mi++)
        #pragma unroll
        for (int h = 0; h < 2; h++) {
            int b = m0 + wm + mi*16 + rq + h*8;
            float inv = g_invn[b];
            #pragma unroll
            for (int ni = 0; ni < 4; ni++) {
                int v = n0 + wn + ni*8 + cq;
                uint32_t wp = *reinterpret_cast<const uint32_t*>(g_bows16 + (size_t)b*VP + v);
                float w0, w1; unp2(wp, w0, w1);
                float d0 = a3[mi][ni][2*h], d1 = a3[mi][ni][2*h+1];
                float r0 = a4[mi][ni][2*h], r1 = a4[mi][ni][2*h+1];
                if (w0 != 0.f) {
                    nF += __fdividef(w0 * inv, d0 + 1e-30f);
                    nT += r0 + c_lg[(int)w0] - w0 * __logf(r0 + 1e-10f);
                } else nT += r0;
                if (w1 != 0.f) {
                    nF += __fdividef(w1 * inv, d1 + 1e-30f);
                    nT += r1 + c_lg[(int)w1] - w1 * __logf(r1 + 1e-10f);
                } else nT += r1;
            }
        }
    __syncthreads();
    float* red = (float*)dsm;
    red[tid] = nF; red[256 + tid] = nT;
    __syncthreads();
    for (int s = 128; s > 0; s >>= 1) {
        if (tid < s) { red[tid] += red[tid+s]; red[256+tid] += red[256+tid+s]; }
        __syncthreads();
    }
    if (tid == 0) {
        g_pF[blockIdx.y*4 + blockIdx.x] = red[0];
        g_pT[blockIdx.y*4 + blockIdx.x] = red[256];
    }
}

// ---------------- converters ----------------
__global__ void k_cvt_bows(const float* __restrict__ bows) {
    int b = blockIdx.x, tid = threadIdx.x;
    float s = 0.f;
    for (int i = tid; i < VP/8; i += 256) {
        int v = i * 8;
        uint4 o = make_uint4(0u,0u,0u,0u);
        if (v < VV) {
            const float4* p = reinterpret_cast<const float4*>(bows + (size_t)b*VV + v);
            float4 a = p[0], c = p[1];
            s += a.x+a.y+a.z+a.w + c.x+c.y+c.z+c.w;
            o.x = pk2(a.x,a.y); o.y = pk2(a.z,a.w); o.z = pk2(c.x,c.y); o.w = pk2(c.z,c.w);
        }
        reinterpret_cast<uint4*>(g_bows16)[(size_t)b*(VP/8) + i] = o;
    }
    __shared__ float red[256];
    red[tid] = s; __syncthreads();
    for (int st = 128; st > 0; st >>= 1) { if (tid < st) red[tid] += red[tid+st]; __syncthreads(); }
    if (tid == 0) { float n = red[0]; g_ntok[b] = n; g_invn[b] = (n > 0.f) ? 1.f/n : 0.f; }
}
__global__ void k_cvt_w1t(const float* __restrict__ W1) {
    __shared__ float t[64][65];
    int tx = threadIdx.x, ty = threadIdx.y;   // (32, 8)
    int v0 = blockIdx.x*64, h0 = blockIdx.y*64;
    #pragma unroll
    for (int i = 0; i < 8; i++) {
        int r = ty + i*8;
        int gv = v0 + r;
        t[r][tx]    = (gv < VV && h0+tx    < HIDD) ? W1[(size_t)gv*HIDD + h0+tx]    : 0.f;
        t[r][tx+32] = (gv < VV && h0+tx+32 < HIDD) ? W1[(size_t)gv*HIDD + h0+tx+32] : 0.f;
    }
    __syncthreads();
    #pragma unroll
    for (int i = 0; i < 8; i++) {
        int r = ty + i*8;          // local h
        uint32_t val = pk2(t[2*tx][r], t[2*tx+1][r]);
        *reinterpret_cast<uint32_t*>(g_w1t + (size_t)(h0+r)*VP + v0 + 2*tx) = val;
    }
}
#define RHO_BLKS ((VV*HP)/256)    // 62500
__global__ void k_cvt_rhoal(const float* __restrict__ rho, const float* __restrict__ al) {
    int bid = blockIdx.x;
    if (bid < RHO_BLKS) {
        int idx = bid*256 + threadIdx.x;
        int r = idx / HP, c = idx % HP;
        g_rho16[idx] = (c < HH) ? __float2bfloat16_rn(rho[(size_t)r*HH + c]) : __nv_bfloat16(0.f);
    } else {
        int idx = (bid - RHO_BLKS)*256 + threadIdx.x;
        int r = idx / HP, c = idx % HP;
        g_al16[idx] = (r < KK && c < HH) ? __float2bfloat16_rn(al[(size_t)r*HH + c]) : __nv_bfloat16(0.f);
    }
}

// ---------------- small kernels ----------------
__global__ void k_sr() {
    int t = threadIdx.x;
    float s = 0.f;
    for (int i = 0; i < MT; i++) s += g_Sp[i*KP + t];
    g_S[t] = s;
}
__global__ void k1_reduce(const float* __restrict__ b1) {
    int idx = blockIdx.x*256 + threadIdx.x;
    if (idx >= BN*HIDD) return;
    int b = idx / HIDD, h = idx % HIDD;
    float s = 0.f;
    #pragma unroll
    for (int z = 0; z < Z1; z++) s += g_p1[(size_t)z*BN*NH + (size_t)b*NH + h];
    g_hid[idx] = fmaxf(s + b1[h], 0.f);
}
__global__ void k_mlp2(const float* __restrict__ W2, const float* __restrict__ b2) {
    __shared__ __align__(16) float As[16][68];
    __shared__ __align__(16) float Bs[16][68];
    const int tid = threadIdx.x, tx = tid & 15, ty = tid >> 4;
    const int m0 = blockIdx.y*64, n0 = blockIdx.x*64;
    const int ar = tid >> 2, ac = (tid & 3) << 2;
    const int br = tid >> 4, bc = (tid & 15) << 2;
    float acc[4][4];
    #pragma unroll
    for (int i = 0; i < 4; i++)
        #pragma unroll
        for (int j = 0; j < 4; j++) acc[i][j] = 0.f;
    for (int kt = 0; kt < 50; ++kt) {
        int k0 = kt*16;
        float4 va = *reinterpret_cast<const float4*>(g_hid + (size_t)(m0+ar)*HIDD + k0 + ac);
        As[ac+0][ar] = va.x; As[ac+1][ar] = va.y; As[ac+2][ar] = va.z; As[ac+3][ar] = va.w;
        float4 vb = make_float4(0.f,0.f,0.f,0.f);
        int gn = n0 + bc;
        const float* bp = W2 + (size_t)(k0+br)*KK + gn;
        if (gn + 3 < KK) vb = *reinterpret_cast<const float4*>(bp);
        else { if (gn<KK) vb.x=bp[0]; if (gn+1<KK) vb.y=bp[1]; if (gn+2<KK) vb.z=bp[2]; }
        *reinterpret_cast<float4*>(&Bs[br][bc]) = vb;
        __syncthreads();
        #pragma unroll
        for (int k = 0; k < 16; k++) {
            float4 a = *reinterpret_cast<const float4*>(&As[k][ty << 2]);
            float4 b = *reinterpret_cast<const float4*>(&Bs[k][tx << 2]);
            float av[4] = {a.x,a.y,a.z,a.w}, bv[4] = {b.x,b.y,b.z,b.w};
            #pragma unroll
            for (int i = 0; i < 4; i++)
                #pragma unroll
                for (int j = 0; j < 4; j++) acc[i][j] = fmaf(av[i], bv[j], acc[i][j]);
        }
        __syncthreads();
    }
    #pragma unroll
    for (int i = 0; i < 4; i++) {
        int m = m0 + (ty << 2) + i;
        #pragma unroll
        for (int j = 0; j < 4; j++) {
            int n = n0 + (tx << 2) + j;
            if (n < KK) {
                float x = acc[i][j] + b2[n];
                g_theta[(size_t)m*KK + n] = fmaxf(x, 0.f) + log1pf(expf(-fabsf(x)));
            }
        }
    }
}
__global__ void k_soft2() {
    int b = blockIdx.x, t = threadIdx.x;   // 256 threads
    __shared__ float red[256];
    float th = (t < KK) ? g_theta[(size_t)b*KK + t] : -1e30f;
    red[t] = th; __syncthreads();
    for (int s = 128; s > 0; s >>= 1) { if (t < s) red[t] = fmaxf(red[t], red[t+s]); __syncthreads(); }
    float mx = red[0]; __syncthreads();
    float e = (t < KK) ? expf(th - mx) : 0.f;
    red[t] = e; __syncthreads();
    for (int s = 128; s > 0; s >>= 1) { if (t < s) red[t] += red[t+s]; __syncthreads(); }
    float tn = e / red[0];
    if (t < KK) g_tn[(size_t)b*KK + t] = tn;
    g_tn16[(size_t)b*KP + t]  = (t < KK) ? __float2bfloat16_rn(tn) : __nv_bfloat16(0.f);
    g_th216[(size_t)b*KP + t] = (t < KK) ? __float2bfloat16_rn(th / g_S[t]) : __nv_bfloat16(0.f);
}
__global__ void k4bwd() {
    int b = blockIdx.x, t = threadIdx.x;
    float local = 0.f;
    if (t < KK) {
        float cs = 0.f;
        #pragma unroll
        for (int z = 0; z < Z2; z++) cs += g_p2[(size_t)z*BN*KP + (size_t)b*KP + t];
        local = g_ntok[b] * g_tn[(size_t)b*KK + t] / (cs + 1e-30f);
    }
    __shared__ float red[256];
    red[t] = local; __syncthreads();
    for (int s = 128; s > 0; s >>= 1) { if (t < s) red[t] += red[t+s]; __syncthreads(); }
    if (t == 0) g_pB[b] = red[0];
}
__global__ void k_final(float* __restrict__ out) {
    int t = threadIdx.x;
    __shared__ double red[256];
    double s = 0.0;
    for (int i = t; i < NP2; i += 256) s += (double)g_pF[i];
    red[t] = s; __syncthreads();
    for (int st = 128; st > 0; st >>= 1) { if (t < st) red[t] += red[t+st]; __syncthreads(); }
    double fwd = red[0]; __syncthreads();
    s = 0.0;
    for (int i = t; i < NP2; i += 256) s += (double)g_pT[i];
    red[t] = s; __syncthreads();
    for (int st = 128; st > 0; st >>= 1) { if (t < st) red[t] += red[t+st]; __syncthreads(); }
    double tm = red[0]; __syncthreads();
    s = 0.0;
    for (int i = t; i < BN; i += 256) s += (double)g_pB[i];
    red[t] = s; __syncthreads();
    for (int st = 128; st > 0; st >>= 1) { if (t < st) red[t] += red[t+st]; __syncthreads(); }
    double bwd = red[0];
    if (t == 0) {
        out[0] = (float)(tm / (double)BN);
        out[1] = (float)(0.5 * fwd);
        out[2] = (float)(0.5 * bwd);
    }
}

// ---------------- launch ----------------
extern "C" void kernel_launch(void* const* d_in, const int* in_sizes, int n_in,
                              void* d_out, int out_size) {
    const float* bows  = (const float*)d_in[0];
    const float* rho   = (const float*)d_in[1];
    const float* alpha = (const float*)d_in[2];
    const float* W1    = (const float*)d_in[3];
    const float* b1    = (const float*)d_in[4];
    const float* W2    = (const float*)d_in[5];
    const float* b2    = (const float*)d_in[6];
    float* out = (float*)d_out;

    static bool attr_done = false;
    if (!attr_done) {
        cudaFuncSetAttribute(mm34, cudaFuncAttributeMaxDynamicSharedMemorySize, 2*STG34);
        attr_done = true;
    }

    // conversions
    k_cvt_bows<<<BN, 256>>>(bows);
    k_cvt_w1t<<<dim3(VP/64, NH/64), dim3(32, 8)>>>(W1);
    k_cvt_rhoal<<<RHO_BLKS + (KP*HP)/256, 256>>>(rho, alpha);

    // dis = clip(exp(rho@alpha^T)) with fused S partials + disT transpose
    mm<0><<<dim3(MT, 2), 256>>>();
    k_sr<<<1, KP>>>();

    // hid = relu(bows@W1 + b1); theta; softmax+th2
    mm<1><<<dim3(4, 7, Z1), 256>>>();
    k1_reduce<<<(BN*HIDD + 255)/256, 256>>>(b1);
    k_mlp2<<<dim3(4, 8), 256>>>(W2, b2);
    k_soft2<<<BN, 256>>>();

    // colsum partials + backward
    mm<2><<<dim3(4, 2, Z2), 256>>>();
    k4bwd<<<BN, 256>>>();

    // merged den+recon with fused reductions
    mm34<<<dim3(4, NT64), 256, 2*STG34>>>();

    k_final<<<1, 256>>>(out);
}

// round 6
// speedup vs baseline: 5.4162x; 1.1004x over previous
#include <cuda_runtime.h>
#include <cuda_bf16.h>
#include <math.h>
#include <stdint.h>

#define BN 512
#define VV 50000
#define KK 200
#define HH 300
#define HIDD 800
#define VP 50048
#define KP 256
#define HP 320
#define NH 896
#define Z1 16
#define Z2 32
#define NKT (VP/32)            // 1564 k-tiles over vocab
#define MT ((VV+127)/128)      // 391 (m-tiles for mm0)
#define NT64 (VP/64)           // 782 (n-tiles for mm34)
#define NP2 (NT64*4)           // 3128 partials

// ---------------- scratch ----------------
__device__ __align__(16) __nv_bfloat16 g_bows16[(size_t)BN*VP];
__device__ __align__(16) __nv_bfloat16 g_w1t[(size_t)NH*VP];
__device__ __align__(16) __nv_bfloat16 g_rho16[(size_t)VV*HP];
__device__ __align__(16) __nv_bfloat16 g_al16[(size_t)KP*HP];
__device__ __align__(16) __nv_bfloat16 g_dis16[(size_t)VV*KP];
__device__ __align__(16) __nv_bfloat16 g_disT16[(size_t)KP*VP];
__device__ __align__(16) __nv_bfloat16 g_tn16[(size_t)BN*KP];
__device__ __align__(16) __nv_bfloat16 g_th216[(size_t)BN*KP];
__device__ float g_p1[(size_t)Z1*BN*NH];
__device__ float g_p2[(size_t)Z2*BN*KP];
__device__ float g_hid[BN*HIDD];
__device__ float g_theta[BN*KK];
__device__ float g_tn[BN*KK];
__device__ float g_ntok[BN];
__device__ float g_invn[BN];
__device__ float g_S[KP];
__device__ float g_Sp[MT*KP];
__device__ float g_pF[NP2];
__device__ float g_pT[NP2];
__device__ float g_pB[BN];

__constant__ float c_lg[5] = {0.0f, 0.0f, 0.69314718055994531f,
                              1.79175946922805500f, 3.17805383034794562f};

// ---------------- helpers ----------------
__device__ __forceinline__ uint32_t s2u(const void* p) {
    uint32_t a;
    asm("{ .reg .u64 t; cvta.to.shared.u64 t, %1; cvt.u32.u64 %0, t; }" : "=r"(a) : "l"(p));
    return a;
}
__device__ __forceinline__ void cpa(uint32_t sa, const void* ga, int sz) {
    asm volatile("cp.async.cg.shared.global [%0], [%1], 16, %2;"
                 :: "r"(sa), "l"(ga), "r"(sz) : "memory");
}
#define CPCOMMIT() asm volatile("cp.async.commit_group;" ::: "memory")
#define CPWAIT(n)  asm volatile("cp.async.wait_group %0;" :: "n"(n) : "memory")
#define LDSM4(r, a) \
    asm volatile("ldmatrix.sync.aligned.m8n8.x4.shared.b16 {%0,%1,%2,%3}, [%4];" \
        : "=r"((r)[0]), "=r"((r)[1]), "=r"((r)[2]), "=r"((r)[3]) : "r"(a))

__device__ __forceinline__ void mma16816(float* c, const uint32_t* a, uint32_t b0, uint32_t b1) {
    asm volatile("mma.sync.aligned.m16n8k16.row.col.f32.bf16.bf16.f32 "
        "{%0,%1,%2,%3}, {%4,%5,%6,%7}, {%8,%9}, {%0,%1,%2,%3};"
        : "+f"(c[0]), "+f"(c[1]), "+f"(c[2]), "+f"(c[3])
        : "r"(a[0]), "r"(a[1]), "r"(a[2]), "r"(a[3]), "r"(b0), "r"(b1));
}
__device__ __forceinline__ void unp2(uint32_t u, float& a, float& b) {
    __nv_bfloat162 t = *reinterpret_cast<__nv_bfloat162*>(&u);
    a = __bfloat162float(t.x); b = __bfloat162float(t.y);
}
__device__ __forceinline__ uint32_t pk2(float a, float b) {
    return ((uint32_t)__bfloat16_as_ushort(__float2bfloat16_rn(b)) << 16) |
            (uint32_t)__bfloat16_as_ushort(__float2bfloat16_rn(a));
}

#define PITCH 80
#define TILEB (128*PITCH)      // 10240
#define STAGEB (2*TILEB)       // 20480

// ---------------- bf16 HMMA GEMM template: C[M,N] = A[M,K] @ B[N,K]^T ----------------
// EPI0: dis = clip(exp(rho@al^T)) + fused S partials + fused disT transpose
// EPI1: p1[z] = bows@w1t^T   split-K Z1
// EPI2: p2[z] = bows@disT^T  split-K Z2
template<int EPI>
__global__ void __launch_bounds__(256) mm() {
    __shared__ __align__(16) char smem[2*STAGEB];
    const uint32_t sb = s2u(smem);
    const int tid = threadIdx.x, lane = tid & 31, wid = tid >> 5;
    const int wm = (wid & 3) * 32, wn = (wid >> 2) * 64;
    const int m0 = blockIdx.x * 128, n0 = blockIdx.y * 128;

    const __nv_bfloat16 *A, *B;
    int lda, ldb, kt0, ktn;
    bool azf = false;
    if (EPI == 0) { A = g_rho16; B = g_al16; lda = HP; ldb = HP; kt0 = 0; ktn = HP/32; azf = true; }
    else if (EPI == 1) { A = g_bows16; B = g_w1t; lda = VP; ldb = VP;
                         kt0 = blockIdx.z * 98; ktn = min(kt0 + 98, NKT) - kt0; }
    else { A = g_bows16; B = g_disT16; lda = VP; ldb = VP;
           kt0 = blockIdx.z * 49; ktn = min(kt0 + 49, NKT) - kt0; }

    auto issue = [&](int it) {
        const int k0 = (kt0 + it) * 32;
        const uint32_t st = sb + (it & 1) * STAGEB;
        #pragma unroll
        for (int i = 0; i < 2; i++) {
            int idx = i * 256 + tid;
            int r = idx >> 2, c = idx & 3;
            int ar = m0 + r;
            bool av = (!azf) || (ar < VV);
            cpa(st + r*PITCH + c*16, A + (size_t)(av ? ar : 0)*lda + k0 + c*8, av ? 16 : 0);
            cpa(st + TILEB + r*PITCH + c*16, B + (size_t)(n0 + r)*ldb + k0 + c*8, 16);
        }
        CPCOMMIT();
    };

    float acc[2][8][4];
    #pragma unroll
    for (int mi = 0; mi < 2; mi++)
        #pragma unroll
        for (int ni = 0; ni < 8; ni++)
            #pragma unroll
            for (int q = 0; q < 4; q++) acc[mi][ni][q] = 0.f;

    issue(0);
    if (ktn > 1) issue(1);

    for (int it = 0; it < ktn; ++it) {
        if (it == ktn - 1) { CPWAIT(0); } else { CPWAIT(1); }
        __syncthreads();
        const uint32_t st = sb + (it & 1) * STAGEB;
        #pragma unroll
        for (int ks = 0; ks < 2; ks++) {
            uint32_t af[2][4], bfm[4][4];
            #pragma unroll
            for (int mi = 0; mi < 2; mi++) {
                int row = wm + mi*16 + (lane & 15);
                LDSM4(af[mi], st + row*PITCH + (ks*2 + (lane >> 4))*16);
            }
            #pragma unroll
            for (int nj = 0; nj < 4; nj++) {
                int row = wn + nj*16 + (lane & 15);
                LDSM4(bfm[nj], st + TILEB + row*PITCH + (ks*2 + (lane >> 4))*16);
            }
            #pragma unroll
            for (int mi = 0; mi < 2; mi++)
                #pragma unroll
                for (int nj = 0; nj < 4; nj++) {
                    mma16816(acc[mi][nj*2],   af[mi], bfm[nj][0], bfm[nj][2]);
                    mma16816(acc[mi][nj*2+1], af[mi], bfm[nj][1], bfm[nj][3]);
                }
        }
        __syncthreads();
        if (it + 2 < ktn) issue(it + 2);
    }

    const int rq = lane >> 2, cq = (lane & 3) * 2;

    if constexpr (EPI == 0) {
        // stage tile (128 x 128 bf16, pitch 130 elems), write dis16 + S partials + disT
        uint32_t* stg = (uint32_t*)smem;
        #pragma unroll
        for (int mi = 0; mi < 2; mi++)
            #pragma unroll
            for (int h = 0; h < 2; h++) {
                int lr = wm + mi*16 + rq + h*8;
                int row = m0 + lr;
                bool rv = row < VV;
                #pragma unroll
                for (int ni = 0; ni < 8; ni++) {
                    int lc = wn + ni*8 + cq;
                    float e0 = rv ? fminf(fmaxf(__expf(acc[mi][ni][2*h]),   1e-30f), 1e10f) : 0.f;
                    float e1 = rv ? fminf(fmaxf(__expf(acc[mi][ni][2*h+1]), 1e-30f), 1e10f) : 0.f;
                    uint32_t pkd = pk2(e0, e1);
                    stg[lr*65 + (lc >> 1)] = pkd;
                    if (rv) *reinterpret_cast<uint32_t*>(g_dis16 + (size_t)row*KP + n0 + lc) = pkd;
                }
            }
        __syncthreads();
        // column sums over staged tile
        {
            const __nv_bfloat16* sg = (const __nv_bfloat16*)smem;
            int col = tid & 127, half = tid >> 7;
            float s = 0.f;
            #pragma unroll 8
            for (int r = 0; r < 64; r++)
                s += __bfloat162float(sg[(half*64 + r)*130 + col]);
            float* red = (float*)(smem + 33280);
            red[tid] = s;
            __syncthreads();
            if (tid < 128) g_Sp[blockIdx.x*KP + n0 + tid] = red[tid] + red[128 + tid];
        }
        // transposed write (coalesced 4B stores)
        {
            const __nv_bfloat16* sg = (const __nv_bfloat16*)smem;
            #pragma unroll
            for (int i = 0; i < 32; i++) {
                int idx = i*256 + tid;
                int c = idx >> 6, rp = idx & 63;
                __nv_bfloat16 a = sg[(2*rp)*130 + c];
                __nv_bfloat16 b = sg[(2*rp + 1)*130 + c];
                uint32_t val = ((uint32_t)__bfloat16_as_ushort(b) << 16) |
                                (uint32_t)__bfloat16_as_ushort(a);
                *reinterpret_cast<uint32_t*>(g_disT16 + (size_t)(n0 + c)*VP + m0 + 2*rp) = val;
            }
        }
    } else {
        constexpr int LDN = (EPI == 1) ? NH : KP;
        float* dst = ((EPI == 1) ? g_p1 : g_p2) + (size_t)blockIdx.z * BN * LDN;
        #pragma unroll
        for (int mi = 0; mi < 2; mi++)
            #pragma unroll
            for (int h = 0; h < 2; h++) {
                int row = m0 + wm + mi*16 + rq + h*8;
                #pragma unroll
                for (int ni = 0; ni < 8; ni++) {
                    int col = n0 + wn + ni*8 + cq;
                    float2 v = make_float2(acc[mi][ni][2*h], acc[mi][ni][2*h+1]);
                    *reinterpret_cast<float2*>(dst + (size_t)row*LDN + col) = v;
                }
            }
    }
}

// ---------------- merged den+recon kernel (dual accumulator) ----------------
#define STG34 25600
__global__ void __launch_bounds__(256) mm34() {
    extern __shared__ __align__(16) char dsm[];
    const uint32_t sb = s2u(dsm);
    const int tid = threadIdx.x, lane = tid & 31, wid = tid >> 5;
    const int wm = (wid & 3) * 32, wn = (wid >> 2) * 32;
    const int m0 = blockIdx.x * 128, n0 = blockIdx.y * 64;

    auto issue = [&](int it) {
        const int k0 = it * 32;
        const uint32_t st = sb + (it & 1) * STG34;
        #pragma unroll
        for (int i = 0; i < 2; i++) {
            int idx = i * 256 + tid;
            int r = idx >> 2, c = idx & 3;
            cpa(st + r*PITCH + c*16,         g_tn16  + (size_t)(m0 + r)*KP + k0 + c*8, 16);
            cpa(st + 10240 + r*PITCH + c*16, g_th216 + (size_t)(m0 + r)*KP + k0 + c*8, 16);
        }
        {
            int r = tid >> 2, c = tid & 3;
            int br = n0 + r;
            bool bv = br < VV;
            cpa(st + 20480 + r*PITCH + c*16, g_dis16 + (size_t)(bv ? br : 0)*KP + k0 + c*8, bv ? 16 : 0);
        }
        CPCOMMIT();
    };

    float a3[2][4][4], a4[2][4][4];
    #pragma unroll
    for (int mi = 0; mi < 2; mi++)
        #pragma unroll
        for (int ni = 0; ni < 4; ni++)
            #pragma unroll
            for (int q = 0; q < 4; q++) { a3[mi][ni][q] = 0.f; a4[mi][ni][q] = 0.f; }

    issue(0); issue(1);
    const int ktn = KP/32;    // 8
    for (int it = 0; it < ktn; ++it) {
        if (it == ktn - 1) { CPWAIT(0); } else { CPWAIT(1); }
        __syncthreads();
        const uint32_t st = sb + (it & 1) * STG34;
        #pragma unroll
        for (int ks = 0; ks < 2; ks++) {
            uint32_t af1[2][4], af2[2][4], bfm[2][4];
            #pragma unroll
            for (int mi = 0; mi < 2; mi++) {
                int row = wm + mi*16 + (lane & 15);
                uint32_t off = row*PITCH + (ks*2 + (lane >> 4))*16;
                LDSM4(af1[mi], st + off);
                LDSM4(af2[mi], st + 10240 + off);
            }
            #pragma unroll
            for (int nj = 0; nj < 2; nj++) {
                int row = wn + nj*16 + (lane & 15);
                LDSM4(bfm[nj], st + 20480 + row*PITCH + (ks*2 + (lane >> 4))*16);
            }
            #pragma unroll
            for (int mi = 0; mi < 2; mi++)
                #pragma unroll
                for (int nj = 0; nj < 2; nj++) {
                    mma16816(a3[mi][nj*2],   af1[mi], bfm[nj][0], bfm[nj][2]);
                    mma16816(a3[mi][nj*2+1], af1[mi], bfm[nj][1], bfm[nj][3]);
                    mma16816(a4[mi][nj*2],   af2[mi], bfm[nj][0], bfm[nj][2]);
                    mma16816(a4[mi][nj*2+1], af2[mi], bfm[nj][1], bfm[nj][3]);
                }
        }
        __syncthreads();
        if (it + 2 < ktn) issue(it + 2);
    }

    const int rq = lane >> 2, cq = (lane & 3) * 2;
    float nF = 0.f, nT = 0.f;
    #pragma unroll
    for (int mi = 0; mi < 2; mi++)
        #pragma unroll
        for (int h = 0; h < 2; h++) {
            int b = m0 + wm + mi*16 + rq + h*8;
            float inv = g_invn[b];
            #pragma unroll
            for (int ni = 0; ni < 4; ni++) {
                int v = n0 + wn + ni*8 + cq;
                uint32_t wp = *reinterpret_cast<const uint32_t*>(g_bows16 + (size_t)b*VP + v);
                float w0, w1; unp2(wp, w0, w1);
                float d0 = a3[mi][ni][2*h], d1 = a3[mi][ni][2*h+1];
                float r0 = a4[mi][ni][2*h], r1 = a4[mi][ni][2*h+1];
                if (w0 != 0.f) {
                    nF += __fdividef(w0 * inv, d0 + 1e-30f);
                    nT += r0 + c_lg[(int)w0] - w0 * __logf(r0 + 1e-10f);
                } else nT += r0;
                if (w1 != 0.f) {
                    nF += __fdividef(w1 * inv, d1 + 1e-30f);
                    nT += r1 + c_lg[(int)w1] - w1 * __logf(r1 + 1e-10f);
                } else nT += r1;
            }
        }
    __syncthreads();
    float* red = (float*)dsm;
    red[tid] = nF; red[256 + tid] = nT;
    __syncthreads();
    for (int s = 128; s > 0; s >>= 1) {
        if (tid < s) { red[tid] += red[tid+s]; red[256+tid] += red[256+tid+s]; }
        __syncthreads();
    }
    if (tid == 0) {
        g_pF[blockIdx.y*4 + blockIdx.x] = red[0];
        g_pT[blockIdx.y*4 + blockIdx.x] = red[256];
    }
}

// ---------------- converters ----------------
__global__ void k_cvt_bows(const float* __restrict__ bows) {
    int b = blockIdx.x, tid = threadIdx.x;
    float s = 0.f;
    for (int i = tid; i < VP/8; i += 256) {
        int v = i * 8;
        uint4 o = make_uint4(0u,0u,0u,0u);
        if (v < VV) {
            const float4* p = reinterpret_cast<const float4*>(bows + (size_t)b*VV + v);
            float4 a = p[0], c = p[1];
            s += a.x+a.y+a.z+a.w + c.x+c.y+c.z+c.w;
            o.x = pk2(a.x,a.y); o.y = pk2(a.z,a.w); o.z = pk2(c.x,c.y); o.w = pk2(c.z,c.w);
        }
        reinterpret_cast<uint4*>(g_bows16)[(size_t)b*(VP/8) + i] = o;
    }
    __shared__ float red[256];
    red[tid] = s; __syncthreads();
    for (int st = 128; st > 0; st >>= 1) { if (tid < st) red[tid] += red[tid+st]; __syncthreads(); }
    if (tid == 0) { float n = red[0]; g_ntok[b] = n; g_invn[b] = (n > 0.f) ? 1.f/n : 0.f; }
}
__global__ void k_cvt_w1t(const float* __restrict__ W1) {
    __shared__ float t[64][65];
    int tx = threadIdx.x, ty = threadIdx.y;   // (32, 8)
    int v0 = blockIdx.x*64, h0 = blockIdx.y*64;
    #pragma unroll
    for (int i = 0; i < 8; i++) {
        int r = ty + i*8;
        int gv = v0 + r;
        t[r][tx]    = (gv < VV && h0+tx    < HIDD) ? W1[(size_t)gv*HIDD + h0+tx]    : 0.f;
        t[r][tx+32] = (gv < VV && h0+tx+32 < HIDD) ? W1[(size_t)gv*HIDD + h0+tx+32] : 0.f;
    }
    __syncthreads();
    #pragma unroll
    for (int i = 0; i < 8; i++) {
        int r = ty + i*8;
        uint32_t val = pk2(t[2*tx][r], t[2*tx+1][r]);
        *reinterpret_cast<uint32_t*>(g_w1t + (size_t)(h0+r)*VP + v0 + 2*tx) = val;
    }
}
#define RHO_BLKS ((VV*HP)/256)    // 62500
__global__ void k_cvt_rhoal(const float* __restrict__ rho, const float* __restrict__ al) {
    int bid = blockIdx.x;
    if (bid < RHO_BLKS) {
        int idx = bid*256 + threadIdx.x;
        int r = idx / HP, c = idx % HP;
        g_rho16[idx] = (c < HH) ? __float2bfloat16_rn(rho[(size_t)r*HH + c]) : __nv_bfloat16(0.f);
    } else {
        int idx = (bid - RHO_BLKS)*256 + threadIdx.x;
        int r = idx / HP, c = idx % HP;
        g_al16[idx] = (r < KK && c < HH) ? __float2bfloat16_rn(al[(size_t)r*HH + c]) : __nv_bfloat16(0.f);
    }
}

// ---------------- small kernels ----------------
__global__ void k_sr() {
    int t = threadIdx.x;
    float s = 0.f;
    for (int i = 0; i < MT; i++) s += g_Sp[i*KP + t];
    g_S[t] = s;
}
__global__ void k1_reduce(const float* __restrict__ b1) {
    int idx = blockIdx.x*256 + threadIdx.x;
    if (idx >= BN*HIDD) return;
    int b = idx / HIDD, h = idx % HIDD;
    float s = 0.f;
    #pragma unroll
    for (int z = 0; z < Z1; z++) s += g_p1[(size_t)z*BN*NH + (size_t)b*NH + h];
    g_hid[idx] = fmaxf(s + b1[h], 0.f);
}
__global__ void k_mlp2(const float* __restrict__ W2, const float* __restrict__ b2) {
    __shared__ __align__(16) float As[16][68];
    __shared__ __align__(16) float Bs[16][68];
    const int tid = threadIdx.x, tx = tid & 15, ty = tid >> 4;
    const int m0 = blockIdx.y*64, n0 = blockIdx.x*64;
    const int ar = tid >> 2, ac = (tid & 3) << 2;
    const int br = tid >> 4, bc = (tid & 15) << 2;
    float acc[4][4];
    #pragma unroll
    for (int i = 0; i < 4; i++)
        #pragma unroll
        for (int j = 0; j < 4; j++) acc[i][j] = 0.f;
    for (int kt = 0; kt < 50; ++kt) {
        int k0 = kt*16;
        float4 va = *reinterpret_cast<const float4*>(g_hid + (size_t)(m0+ar)*HIDD + k0 + ac);
        As[ac+0][ar] = va.x; As[ac+1][ar] = va.y; As[ac+2][ar] = va.z; As[ac+3][ar] = va.w;
        float4 vb = make_float4(0.f,0.f,0.f,0.f);
        int gn = n0 + bc;
        const float* bp = W2 + (size_t)(k0+br)*KK + gn;
        if (gn + 3 < KK) vb = *reinterpret_cast<const float4*>(bp);
        else { if (gn<KK) vb.x=bp[0]; if (gn+1<KK) vb.y=bp[1]; if (gn+2<KK) vb.z=bp[2]; }
        *reinterpret_cast<float4*>(&Bs[br][bc]) = vb;
        __syncthreads();
        #pragma unroll
        for (int k = 0; k < 16; k++) {
            float4 a = *reinterpret_cast<const float4*>(&As[k][ty << 2]);
            float4 b = *reinterpret_cast<const float4*>(&Bs[k][tx << 2]);
            float av[4] = {a.x,a.y,a.z,a.w}, bv[4] = {b.x,b.y,b.z,b.w};
            #pragma unroll
            for (int i = 0; i < 4; i++)
                #pragma unroll
                for (int j = 0; j < 4; j++) acc[i][j] = fmaf(av[i], bv[j], acc[i][j]);
        }
        __syncthreads();
    }
    #pragma unroll
    for (int i = 0; i < 4; i++) {
        int m = m0 + (ty << 2) + i;
        #pragma unroll
        for (int j = 0; j < 4; j++) {
            int n = n0 + (tx << 2) + j;
            if (n < KK) {
                float x = acc[i][j] + b2[n];
                g_theta[(size_t)m*KK + n] = fmaxf(x, 0.f) + log1pf(expf(-fabsf(x)));
            }
        }
    }
}
__global__ void k_soft2() {
    int b = blockIdx.x, t = threadIdx.x;
    __shared__ float red[256];
    float th = (t < KK) ? g_theta[(size_t)b*KK + t] : -1e30f;
    red[t] = th; __syncthreads();
    for (int s = 128; s > 0; s >>= 1) { if (t < s) red[t] = fmaxf(red[t], red[t+s]); __syncthreads(); }
    float mx = red[0]; __syncthreads();
    float e = (t < KK) ? expf(th - mx) : 0.f;
    red[t] = e; __syncthreads();
    for (int s = 128; s > 0; s >>= 1) { if (t < s) red[t] += red[t+s]; __syncthreads(); }
    float tn = e / red[0];
    if (t < KK) g_tn[(size_t)b*KK + t] = tn;
    g_tn16[(size_t)b*KP + t]  = (t < KK) ? __float2bfloat16_rn(tn) : __nv_bfloat16(0.f);
    g_th216[(size_t)b*KP + t] = (t < KK) ? __float2bfloat16_rn(th / g_S[t]) : __nv_bfloat16(0.f);
}
__global__ void k4bwd() {
    int b = blockIdx.x, t = threadIdx.x;
    float local = 0.f;
    if (t < KK) {
        float cs = 0.f;
        #pragma unroll
        for (int z = 0; z < Z2; z++) cs += g_p2[(size_t)z*BN*KP + (size_t)b*KP + t];
        local = g_ntok[b] * g_tn[(size_t)b*KK + t] / (cs + 1e-30f);
    }
    __shared__ float red[256];
    red[t] = local; __syncthreads();
    for (int s = 128; s > 0; s >>= 1) { if (t < s) red[t] += red[t+s]; __syncthreads(); }
    if (t == 0) g_pB[b] = red[0];
}
__global__ void k_final(float* __restrict__ out) {
    int t = threadIdx.x;
    __shared__ double red[256];
    double s = 0.0;
    for (int i = t; i < NP2; i += 256) s += (double)g_pF[i];
    red[t] = s; __syncthreads();
    for (int st = 128; st > 0; st >>= 1) { if (t < st) red[t] += red[t+st]; __syncthreads(); }
    double fwd = red[0]; __syncthreads();
    s = 0.0;
    for (int i = t; i < NP2; i += 256) s += (double)g_pT[i];
    red[t] = s; __syncthreads();
    for (int st = 128; st > 0; st >>= 1) { if (t < st) red[t] += red[t+st]; __syncthreads(); }
    double tm = red[0]; __syncthreads();
    s = 0.0;
    for (int i = t; i < BN; i += 256) s += (double)g_pB[i];
    red[t] = s; __syncthreads();
    for (int st = 128; st > 0; st >>= 1) { if (t < st) red[t] += red[t+st]; __syncthreads(); }
    double bwd = red[0];
    if (t == 0) {
        out[0] = (float)(tm / (double)BN);
        out[1] = (float)(0.5 * fwd);
        out[2] = (float)(0.5 * bwd);
    }
}

// ---------------- launch (two-stream fork/join, graph-capturable) ----------------
extern "C" void kernel_launch(void* const* d_in, const int* in_sizes, int n_in,
                              void* d_out, int out_size) {
    const float* bows  = (const float*)d_in[0];
    const float* rho   = (const float*)d_in[1];
    const float* alpha = (const float*)d_in[2];
    const float* W1    = (const float*)d_in[3];
    const float* b1    = (const float*)d_in[4];
    const float* W2    = (const float*)d_in[5];
    const float* b2    = (const float*)d_in[6];
    float* out = (float*)d_out;

    static cudaStream_t s1 = nullptr;
    static cudaEvent_t evF, evB, evS, evJ;
    if (!s1) {
        cudaStreamCreateWithFlags(&s1, cudaStreamNonBlocking);
        cudaEventCreateWithFlags(&evF, cudaEventDisableTiming);
        cudaEventCreateWithFlags(&evB, cudaEventDisableTiming);
        cudaEventCreateWithFlags(&evS, cudaEventDisableTiming);
        cudaEventCreateWithFlags(&evJ, cudaEventDisableTiming);
        cudaFuncSetAttribute(mm34, cudaFuncAttributeMaxDynamicSharedMemorySize, 2*STG34);
    }

    // fork chain A onto s1
    cudaEventRecord(evF, 0);
    cudaStreamWaitEvent(s1, evF, 0);

    // chain A (s1): rho/alpha convert -> dis GEMM (+S partials, disT) -> S reduce
    k_cvt_rhoal<<<RHO_BLKS + (KP*HP)/256, 256, 0, s1>>>(rho, alpha);
    mm<0><<<dim3(MT, 2), 256, 0, s1>>>();
    k_sr<<<1, KP, 0, s1>>>();
    cudaEventRecord(evS, s1);

    // chain B (default): bows convert (+ntok)
    k_cvt_bows<<<BN, 256>>>(bows);
    cudaEventRecord(evB, 0);

    // chain A continues: colsum GEMM needs bows16 + disT16
    cudaStreamWaitEvent(s1, evB, 0);
    mm<2><<<dim3(4, 2, Z2), 256, 0, s1>>>();
    cudaEventRecord(evJ, s1);

    // chain B: W1 convert -> hid GEMM -> reduce -> mlp2
    k_cvt_w1t<<<dim3(VP/64, NH/64), dim3(32, 8)>>>(W1);
    mm<1><<<dim3(4, 7, Z1), 256>>>();
    k1_reduce<<<(BN*HIDD + 255)/256, 256>>>(b1);
    k_mlp2<<<dim3(4, 8), 256>>>(W2, b2);

    // join: soft2 needs g_S (chain A)
    cudaStreamWaitEvent(0, evS, 0);
    k_soft2<<<BN, 256>>>();

    // join: k4bwd needs p2 (chain A mm<2>)
    cudaStreamWaitEvent(0, evJ, 0);
    k4bwd<<<BN, 256>>>();

    // merged den+recon with fused reductions
    mm34<<<dim3(4, NT64), 256, 2*STG34>>>();

    k_final<<<1, 256>>>(out);
}